// round 7
// baseline (speedup 1.0000x reference)
#include <cuda_runtime.h>

#define EMB 1024
#define DKH 64
#define NB 4
#define SL 4096
#define MTOT (NB*SL)
#define NSPLIT 4
#define KEYS_PER_SPLIT (SL/NSPLIT)

// ---------------- scratch (no allocations allowed) ----------------
// Q/K/V stored as tf32 bits, d-transposed within each 64-wide row:
//   element (row, d) lives at word  row*64 + (d%8)*8 + d/8
__device__ unsigned g_Q[MTOT*DKH];
__device__ unsigned g_K[MTOT*DKH];
__device__ unsigned g_V[MTOT*DKH];
__device__ float    g_part[(size_t)NSPLIT*MTOT*DKH];  // unnormalized partial O
__device__ float    g_ml[(size_t)NSPLIT*MTOT*2];      // (m, l) per split per row

// ---------------- helpers ----------------
__device__ __forceinline__ unsigned f2tf(float f){
    unsigned u; asm("cvt.rna.tf32.f32 %0, %1;" : "=r"(u) : "f"(f)); return u;
}
__device__ __forceinline__ float ex2(float x){
    float y; asm("ex2.approx.ftz.f32 %0, %1;" : "=f"(y) : "f"(x)); return y;
}
__device__ __forceinline__ void mma8(float* c,
        unsigned a0, unsigned a1, unsigned a2, unsigned a3,
        unsigned b0, unsigned b1){
    asm volatile(
        "mma.sync.aligned.m16n8k8.row.col.f32.tf32.tf32.f32 "
        "{%0,%1,%2,%3},{%4,%5,%6,%7},{%8,%9},{%0,%1,%2,%3};"
        : "+f"(c[0]), "+f"(c[1]), "+f"(c[2]), "+f"(c[3])
        : "r"(a0), "r"(a1), "r"(a2), "r"(a3), "r"(b0), "r"(b1));
}

// Epilogue store: bias + scale, tf32 convert, d-transposed layout.
// acc frag (i,j,e): row = row0+wm*32+i*16+g (+8 for e in {2,3}),
// col c = wn*32+j*8+2tg (+1 for odd e)  ->  d' = 16tg + 4wn + j (+8 for odd e).
__device__ __forceinline__ void store_proj(unsigned* out, float acc[2][4][4],
        const float* __restrict__ bias, float scale,
        int row0, int wm, int wn, int g, int tg)
{
    #pragma unroll
    for (int i = 0; i < 2; i++) {
        int r0 = row0 + wm*32 + i*16 + g;
        unsigned lo0[4], hi0[4], lo1[4], hi1[4];
        #pragma unroll
        for (int j = 0; j < 4; j++) {
            int c = wn*32 + j*8 + 2*tg;
            float b0 = bias[c], b1 = bias[c+1];
            lo0[j] = f2tf((acc[i][j][0] + b0) * scale);
            hi0[j] = f2tf((acc[i][j][1] + b1) * scale);
            lo1[j] = f2tf((acc[i][j][2] + b0) * scale);
            hi1[j] = f2tf((acc[i][j][3] + b1) * scale);
        }
        unsigned* p0 = out + (size_t)r0 * DKH + 16*tg + 4*wn;
        *(uint4*)(p0)     = make_uint4(lo0[0], lo0[1], lo0[2], lo0[3]);
        *(uint4*)(p0 + 8) = make_uint4(hi0[0], hi0[1], hi0[2], hi0[3]);
        unsigned* p1 = out + (size_t)(r0 + 8) * DKH + 16*tg + 4*wn;
        *(uint4*)(p1)     = make_uint4(lo1[0], lo1[1], lo1[2], lo1[3]);
        *(uint4*)(p1 + 8) = make_uint4(hi1[0], hi1[1], hi1[2], hi1[3]);
    }
}

// ============================================================================
// Kernel 1a: Q projection (reads input2). Scale = 1/8 * log2(e)  (exp2 domain).
// ============================================================================
__global__ __launch_bounds__(256) void proj_q_kernel(
    const float* __restrict__ in2,
    const float* __restrict__ Wq, const float* __restrict__ bq)
{
    __shared__ unsigned As[128*36];
    __shared__ unsigned Bs[32*72];

    const int tid = threadIdx.x;
    const int lane = tid & 31, wid = tid >> 5;
    const int g = lane >> 2, tg = lane & 3;
    const int wm = wid & 3, wn = wid >> 2;
    const int row0 = blockIdx.x * 128;

    float acc[2][4][4];
    #pragma unroll
    for (int i = 0; i < 2; i++)
        #pragma unroll
        for (int j = 0; j < 4; j++)
            #pragma unroll
            for (int e = 0; e < 4; e++) acc[i][j][e] = 0.f;

    for (int kc = 0; kc < EMB; kc += 32) {
        #pragma unroll
        for (int i = 0; i < 4; i++) {
            int idx = tid + i*256;
            int r = idx >> 3, c = (idx & 7) * 4;
            float4 v = *(const float4*)(in2 + (size_t)(row0 + r)*EMB + kc + c);
            *(uint4*)(As + r*36 + c) =
                make_uint4(f2tf(v.x), f2tf(v.y), f2tf(v.z), f2tf(v.w));
        }
        #pragma unroll
        for (int i = 0; i < 2; i++) {
            int idx = tid + i*256;
            int r = idx >> 4, c = (idx & 15) * 4;
            float4 v = *(const float4*)(Wq + (size_t)(kc + r)*DKH + c);
            *(uint4*)(Bs + r*72 + c) =
                make_uint4(f2tf(v.x), f2tf(v.y), f2tf(v.z), f2tf(v.w));
        }
        __syncthreads();

        #pragma unroll
        for (int ks = 0; ks < 4; ks++) {
            unsigned a[2][4];
            #pragma unroll
            for (int i = 0; i < 2; i++) {
                const unsigned* ap = As + (wm*32 + i*16 + g)*36 + ks*8 + tg;
                a[i][0] = ap[0]; a[i][1] = ap[8*36];
                a[i][2] = ap[4]; a[i][3] = ap[8*36 + 4];
            }
            unsigned bf[4][2];
            #pragma unroll
            for (int j = 0; j < 4; j++) {
                const unsigned* bp = Bs + (ks*8 + tg)*72 + wn*32 + j*8 + g;
                bf[j][0] = bp[0]; bf[j][1] = bp[4*72];
            }
            #pragma unroll
            for (int i = 0; i < 2; i++)
                #pragma unroll
                for (int j = 0; j < 4; j++)
                    mma8(acc[i][j], a[i][0], a[i][1], a[i][2], a[i][3],
                         bf[j][0], bf[j][1]);
        }
        __syncthreads();
    }
    const float QSCALE = 0.125f * 1.44269504088896340736f;  // 1/sqrt(dk) * log2(e)
    store_proj(g_Q, acc, bq, QSCALE, row0, wm, wn, g, tg);
}

// ============================================================================
// Kernel 1b: fused K+V projection (reads input1 ONCE, shared A tile).
// ============================================================================
__global__ __launch_bounds__(256) void proj_kv_kernel(
    const float* __restrict__ in1,
    const float* __restrict__ Wk, const float* __restrict__ bk,
    const float* __restrict__ Wv, const float* __restrict__ bv)
{
    __shared__ unsigned As[128*36];
    __shared__ unsigned Bk[32*72];
    __shared__ unsigned Bv[32*72];

    const int tid = threadIdx.x;
    const int lane = tid & 31, wid = tid >> 5;
    const int g = lane >> 2, tg = lane & 3;
    const int wm = wid & 3, wn = wid >> 2;
    const int row0 = blockIdx.x * 128;

    float ak[2][4][4], av[2][4][4];
    #pragma unroll
    for (int i = 0; i < 2; i++)
        #pragma unroll
        for (int j = 0; j < 4; j++)
            #pragma unroll
            for (int e = 0; e < 4; e++) { ak[i][j][e] = 0.f; av[i][j][e] = 0.f; }

    for (int kc = 0; kc < EMB; kc += 32) {
        #pragma unroll
        for (int i = 0; i < 4; i++) {
            int idx = tid + i*256;
            int r = idx >> 3, c = (idx & 7) * 4;
            float4 v = *(const float4*)(in1 + (size_t)(row0 + r)*EMB + kc + c);
            *(uint4*)(As + r*36 + c) =
                make_uint4(f2tf(v.x), f2tf(v.y), f2tf(v.z), f2tf(v.w));
        }
        #pragma unroll
        for (int i = 0; i < 2; i++) {
            int idx = tid + i*256;
            int r = idx >> 4, c = (idx & 15) * 4;
            float4 vk = *(const float4*)(Wk + (size_t)(kc + r)*DKH + c);
            *(uint4*)(Bk + r*72 + c) =
                make_uint4(f2tf(vk.x), f2tf(vk.y), f2tf(vk.z), f2tf(vk.w));
            float4 vv = *(const float4*)(Wv + (size_t)(kc + r)*DKH + c);
            *(uint4*)(Bv + r*72 + c) =
                make_uint4(f2tf(vv.x), f2tf(vv.y), f2tf(vv.z), f2tf(vv.w));
        }
        __syncthreads();

        #pragma unroll
        for (int ks = 0; ks < 4; ks++) {
            unsigned a[2][4];
            #pragma unroll
            for (int i = 0; i < 2; i++) {
                const unsigned* ap = As + (wm*32 + i*16 + g)*36 + ks*8 + tg;
                a[i][0] = ap[0]; a[i][1] = ap[8*36];
                a[i][2] = ap[4]; a[i][3] = ap[8*36 + 4];
            }
            unsigned fk[4][2], fv[4][2];
            #pragma unroll
            for (int j = 0; j < 4; j++) {
                const unsigned* kp = Bk + (ks*8 + tg)*72 + wn*32 + j*8 + g;
                fk[j][0] = kp[0]; fk[j][1] = kp[4*72];
                const unsigned* vp = Bv + (ks*8 + tg)*72 + wn*32 + j*8 + g;
                fv[j][0] = vp[0]; fv[j][1] = vp[4*72];
            }
            #pragma unroll
            for (int i = 0; i < 2; i++)
                #pragma unroll
                for (int j = 0; j < 4; j++) {
                    mma8(ak[i][j], a[i][0], a[i][1], a[i][2], a[i][3],
                         fk[j][0], fk[j][1]);
                    mma8(av[i][j], a[i][0], a[i][1], a[i][2], a[i][3],
                         fv[j][0], fv[j][1]);
                }
        }
        __syncthreads();
    }
    store_proj(g_K, ak, bk, 1.0f, row0, wm, wn, g, tg);
    store_proj(g_V, av, bv, 1.0f, row0, wm, wn, g, tg);
}

// ============================================================================
// Kernel 2: flash attention with 4-way key split.
// grid = (SL/128, NB, NSPLIT); 256 threads; 2 CTAs/SM target.
// All frag gathers are LDS.128 thanks to the d-transposed tf32 layout.
// ============================================================================
#define SK 68
#define SMEM_ATTN ((64*SK + 64*SK + 8*16*SK) * 4)   // 69632 B

__global__ __launch_bounds__(256, 2) void attn_kernel()
{
    extern __shared__ unsigned smem[];
    unsigned* Ks = smem;                 // [64][SK]
    unsigned* Vs = smem + 64*SK;         // [64][SK]
    unsigned* Ps = smem + 128*SK;        // [8 warps][16][SK], key-transposed

    const int tid = threadIdx.x;
    const int lane = tid & 31, wid = tid >> 5;
    const int g = lane >> 2, tg = lane & 3;
    const int b = blockIdx.y;
    const int split = blockIdx.z;

    const unsigned* Qg = g_Q + ((size_t)b*SL + blockIdx.x*128 + wid*16) * DKH;
    const unsigned* Kg = g_K + ((size_t)b*SL + split*KEYS_PER_SPLIT) * DKH;
    const unsigned* Vg = g_V + ((size_t)b*SL + split*KEYS_PER_SPLIT) * DKH;
    unsigned* Pw = Ps + wid*16*SK;

    float o[8][4];
    #pragma unroll
    for (int dt = 0; dt < 8; dt++)
        #pragma unroll
        for (int e = 0; e < 4; e++) o[dt][e] = 0.f;

    float m0 = -3.402823466e38f, m1 = -3.402823466e38f;
    float l0 = 0.f, l1 = 0.f;

    for (int k0 = 0; k0 < KEYS_PER_SPLIT; k0 += 64) {
        // ---- tile load: already tf32 + transposed, pure uint4 copy ----
        #pragma unroll
        for (int i = 0; i < 4; i++) {
            int idx = tid + i*256;
            int r = idx >> 4, cu = (idx & 15) * 4;
            *(uint4*)(Ks + r*SK + cu) = *(const uint4*)(Kg + (size_t)(k0+r)*DKH + cu);
            *(uint4*)(Vs + r*SK + cu) = *(const uint4*)(Vg + (size_t)(k0+r)*DKH + cu);
        }
        __syncthreads();

        // ---- Q frags (re-read per tile from L1-hot global; short liveness) ----
        unsigned ql0[8], ql1[8], qh0[8], qh1[8];
        {
            const unsigned* q0 = Qg + (size_t)g * DKH;
            const unsigned* q1 = Qg + (size_t)(g + 8) * DKH;
            *(uint4*)(ql0)     = *(const uint4*)(q0 + tg*8);
            *(uint4*)(ql0 + 4) = *(const uint4*)(q0 + tg*8 + 4);
            *(uint4*)(qh0)     = *(const uint4*)(q0 + tg*8 + 32);
            *(uint4*)(qh0 + 4) = *(const uint4*)(q0 + tg*8 + 36);
            *(uint4*)(ql1)     = *(const uint4*)(q1 + tg*8);
            *(uint4*)(ql1 + 4) = *(const uint4*)(q1 + tg*8 + 4);
            *(uint4*)(qh1)     = *(const uint4*)(q1 + tg*8 + 32);
            *(uint4*)(qh1 + 4) = *(const uint4*)(q1 + tg*8 + 36);
        }

        // ---- S = Q @ K^T ----
        float s[8][4];
        #pragma unroll
        for (int nt = 0; nt < 8; nt++) {
            const unsigned* kb = Ks + (nt*8 + g)*SK + tg*8;
            unsigned kl[8], kh[8];
            *(uint4*)(kl)     = *(const uint4*)(kb);
            *(uint4*)(kl + 4) = *(const uint4*)(kb + 4);
            *(uint4*)(kh)     = *(const uint4*)(kb + 32);
            *(uint4*)(kh + 4) = *(const uint4*)(kb + 36);
            s[nt][0] = s[nt][1] = s[nt][2] = s[nt][3] = 0.f;
            #pragma unroll
            for (int dk = 0; dk < 8; dk++)
                mma8(s[nt], ql0[dk], ql1[dk], qh0[dk], qh1[dk], kl[dk], kh[dk]);
        }

        // ---- online softmax (log2 domain; scale pre-folded into Q) ----
        float mx0 = m0, mx1 = m1;
        #pragma unroll
        for (int nt = 0; nt < 8; nt++) {
            mx0 = fmaxf(mx0, fmaxf(s[nt][0], s[nt][1]));
            mx1 = fmaxf(mx1, fmaxf(s[nt][2], s[nt][3]));
        }
        mx0 = fmaxf(mx0, __shfl_xor_sync(0xffffffffu, mx0, 1));
        mx0 = fmaxf(mx0, __shfl_xor_sync(0xffffffffu, mx0, 2));
        mx1 = fmaxf(mx1, __shfl_xor_sync(0xffffffffu, mx1, 1));
        mx1 = fmaxf(mx1, __shfl_xor_sync(0xffffffffu, mx1, 2));

        float f0 = ex2(m0 - mx0);
        float f1 = ex2(m1 - mx1);

        float sum0 = 0.f, sum1 = 0.f;
        #pragma unroll
        for (int nt = 0; nt < 8; nt++) {
            s[nt][0] = ex2(s[nt][0] - mx0);
            s[nt][1] = ex2(s[nt][1] - mx0);
            s[nt][2] = ex2(s[nt][2] - mx1);
            s[nt][3] = ex2(s[nt][3] - mx1);
            sum0 += s[nt][0] + s[nt][1];
            sum1 += s[nt][2] + s[nt][3];
        }
        sum0 += __shfl_xor_sync(0xffffffffu, sum0, 1);
        sum0 += __shfl_xor_sync(0xffffffffu, sum0, 2);
        sum1 += __shfl_xor_sync(0xffffffffu, sum1, 1);
        sum1 += __shfl_xor_sync(0xffffffffu, sum1, 2);

        l0 = l0 * f0 + sum0;
        l1 = l1 * f1 + sum1;
        m0 = mx0; m1 = mx1;

        #pragma unroll
        for (int dt = 0; dt < 8; dt++) {
            o[dt][0] *= f0; o[dt][1] *= f0;
            o[dt][2] *= f1; o[dt][3] *= f1;
        }

        // ---- P -> smem, key-transposed: word 16tg+nt (=col 8nt+2tg), +8 (odd col) ----
        {
            unsigned* p0 = Pw + g*SK + 16*tg;
            *(uint4*)(p0)      = make_uint4(f2tf(s[0][0]), f2tf(s[1][0]), f2tf(s[2][0]), f2tf(s[3][0]));
            *(uint4*)(p0 + 4)  = make_uint4(f2tf(s[4][0]), f2tf(s[5][0]), f2tf(s[6][0]), f2tf(s[7][0]));
            *(uint4*)(p0 + 8)  = make_uint4(f2tf(s[0][1]), f2tf(s[1][1]), f2tf(s[2][1]), f2tf(s[3][1]));
            *(uint4*)(p0 + 12) = make_uint4(f2tf(s[4][1]), f2tf(s[5][1]), f2tf(s[6][1]), f2tf(s[7][1]));
            unsigned* p1 = Pw + (g + 8)*SK + 16*tg;
            *(uint4*)(p1)      = make_uint4(f2tf(s[0][2]), f2tf(s[1][2]), f2tf(s[2][2]), f2tf(s[3][2]));
            *(uint4*)(p1 + 4)  = make_uint4(f2tf(s[4][2]), f2tf(s[5][2]), f2tf(s[6][2]), f2tf(s[7][2]));
            *(uint4*)(p1 + 8)  = make_uint4(f2tf(s[0][3]), f2tf(s[1][3]), f2tf(s[2][3]), f2tf(s[3][3]));
            *(uint4*)(p1 + 12) = make_uint4(f2tf(s[4][3]), f2tf(s[5][3]), f2tf(s[6][3]), f2tf(s[7][3]));
        }
        __syncwarp();

        // ---- P frags (all 8 k-steps at once, 8x LDS.128) ----
        unsigned pl0[8], pl1[8], ph0[8], ph1[8];
        {
            const unsigned* pr0 = Pw + g*SK;
            const unsigned* pr1 = Pw + (g + 8)*SK;
            *(uint4*)(pl0)     = *(const uint4*)(pr0 + tg*8);
            *(uint4*)(pl0 + 4) = *(const uint4*)(pr0 + tg*8 + 4);
            *(uint4*)(ph0)     = *(const uint4*)(pr0 + tg*8 + 32);
            *(uint4*)(ph0 + 4) = *(const uint4*)(pr0 + tg*8 + 36);
            *(uint4*)(pl1)     = *(const uint4*)(pr1 + tg*8);
            *(uint4*)(pl1 + 4) = *(const uint4*)(pr1 + tg*8 + 4);
            *(uint4*)(ph1)     = *(const uint4*)(pr1 + tg*8 + 32);
            *(uint4*)(ph1 + 4) = *(const uint4*)(pr1 + tg*8 + 36);
        }

        // ---- O += P @ V ----
        #pragma unroll
        for (int kk = 0; kk < 8; kk++) {
            const unsigned* vb0 = Vs + (kk*8 + tg)*SK + g*8;
            const unsigned* vb1 = vb0 + 4*SK;
            unsigned vl[8], vh[8];
            *(uint4*)(vl)     = *(const uint4*)(vb0);
            *(uint4*)(vl + 4) = *(const uint4*)(vb0 + 4);
            *(uint4*)(vh)     = *(const uint4*)(vb1);
            *(uint4*)(vh + 4) = *(const uint4*)(vb1 + 4);
            #pragma unroll
            for (int dt = 0; dt < 8; dt++)
                mma8(o[dt], pl0[kk], pl1[kk], ph0[kk], ph1[kk], vl[dt], vh[dt]);
        }
        __syncthreads();
    }

    // ---- partial epilogue: unnormalized O + (m, l) ----
    size_t base = (size_t)split*MTOT + (size_t)b*SL + blockIdx.x*128 + wid*16;
    float* O0 = g_part + (base + g) * DKH;
    float* O1 = g_part + (base + g + 8) * DKH;
    #pragma unroll
    for (int dt = 0; dt < 8; dt++) {
        int c = dt*8 + 2*tg;
        *(float2*)(O0 + c) = make_float2(o[dt][0], o[dt][1]);
        *(float2*)(O1 + c) = make_float2(o[dt][2], o[dt][3]);
    }
    if (tg == 0) {
        g_ml[(base + g)*2]     = m0;
        g_ml[(base + g)*2 + 1] = l0;
        g_ml[(base + g + 8)*2]     = m1;
        g_ml[(base + g + 8)*2 + 1] = l1;
    }
}

// ============================================================================
// Kernel 3: split merge.  One thread per float2 of output.
// ============================================================================
__global__ __launch_bounds__(256) void merge_kernel(float* __restrict__ out)
{
    int t = blockIdx.x * 256 + threadIdx.x;      // MTOT*32 threads
    int row = t >> 5;
    int cp  = (t & 31) * 2;

    float m[NSPLIT], l[NSPLIT];
    #pragma unroll
    for (int s = 0; s < NSPLIT; s++) {
        m[s] = g_ml[((size_t)s*MTOT + row)*2];
        l[s] = g_ml[((size_t)s*MTOT + row)*2 + 1];
    }
    float M = m[0];
    #pragma unroll
    for (int s = 1; s < NSPLIT; s++) M = fmaxf(M, m[s]);
    float w[NSPLIT], L = 0.f;
    #pragma unroll
    for (int s = 0; s < NSPLIT; s++) { w[s] = ex2(m[s] - M); L += w[s]*l[s]; }

    float ax = 0.f, ay = 0.f;
    #pragma unroll
    for (int s = 0; s < NSPLIT; s++) {
        float2 v = *(const float2*)(g_part + ((size_t)s*MTOT + row)*DKH + cp);
        ax += w[s]*v.x; ay += w[s]*v.y;
    }
    float invL = 1.f / L;
    *(float2*)(out + (size_t)row*DKH + cp) = make_float2(ax*invL, ay*invL);
}

// ============================================================================
extern "C" void kernel_launch(void* const* d_in, const int* in_sizes, int n_in,
                              void* d_out, int out_size)
{
    const float* in1 = (const float*)d_in[0];
    const float* in2 = (const float*)d_in[1];
    const float* Wq  = (const float*)d_in[2];
    const float* bq  = (const float*)d_in[3];
    const float* Wk  = (const float*)d_in[4];
    const float* bk  = (const float*)d_in[5];
    const float* Wv  = (const float*)d_in[6];
    const float* bv  = (const float*)d_in[7];
    float* out = (float*)d_out;

    cudaFuncSetAttribute(attn_kernel,
                         cudaFuncAttributeMaxDynamicSharedMemorySize, SMEM_ATTN);

    proj_q_kernel <<<MTOT/128, 256>>>(in2, Wq, bq);
    proj_kv_kernel<<<MTOT/128, 256>>>(in1, Wk, bk, Wv, bv);
    attn_kernel<<<dim3(SL/128, NB, NSPLIT), 256, SMEM_ATTN>>>();
    merge_kernel<<<(MTOT*32)/256, 256>>>(out);
}

// round 9
// speedup vs baseline: 1.0198x; 1.0198x over previous
#include <cuda_runtime.h>

#define EMB 1024
#define DKH 64
#define NB 4
#define SL 4096
#define MTOT (NB*SL)

// ---------------- scratch (no allocations allowed) ----------------
// Q/K/V stored as tf32 bits, d-transposed within each 64-wide row:
//   element (row, d) lives at word  row*64 + (d%8)*8 + d/8
__device__ unsigned g_Q[MTOT*DKH];
__device__ unsigned g_K[MTOT*DKH];
__device__ unsigned g_V[MTOT*DKH];

// ---------------- helpers ----------------
__device__ __forceinline__ unsigned f2tf(float f){
    unsigned u; asm("cvt.rna.tf32.f32 %0, %1;" : "=r"(u) : "f"(f)); return u;
}
__device__ __forceinline__ float ex2(float x){
    float y; asm("ex2.approx.ftz.f32 %0, %1;" : "=f"(y) : "f"(x)); return y;
}
__device__ __forceinline__ void mma8(float* c,
        unsigned a0, unsigned a1, unsigned a2, unsigned a3,
        unsigned b0, unsigned b1){
    asm volatile(
        "mma.sync.aligned.m16n8k8.row.col.f32.tf32.tf32.f32 "
        "{%0,%1,%2,%3},{%4,%5,%6,%7},{%8,%9},{%0,%1,%2,%3};"
        : "+f"(c[0]), "+f"(c[1]), "+f"(c[2]), "+f"(c[3])
        : "r"(a0), "r"(a1), "r"(a2), "r"(a3), "r"(b0), "r"(b1));
}

// Epilogue store: bias + scale, tf32 convert, d-transposed layout (VALIDATED R7).
__device__ __forceinline__ void store_proj(unsigned* out, float acc[2][4][4],
        const float* __restrict__ bias, float scale,
        int row0, int wm, int wn, int g, int tg)
{
    #pragma unroll
    for (int i = 0; i < 2; i++) {
        int r0 = row0 + wm*32 + i*16 + g;
        unsigned lo0[4], hi0[4], lo1[4], hi1[4];
        #pragma unroll
        for (int j = 0; j < 4; j++) {
            int c = wn*32 + j*8 + 2*tg;
            float b0 = bias[c], b1 = bias[c+1];
            lo0[j] = f2tf((acc[i][j][0] + b0) * scale);
            hi0[j] = f2tf((acc[i][j][1] + b1) * scale);
            lo1[j] = f2tf((acc[i][j][2] + b0) * scale);
            hi1[j] = f2tf((acc[i][j][3] + b1) * scale);
        }
        unsigned* p0 = out + (size_t)r0 * DKH + 16*tg + 4*wn;
        *(uint4*)(p0)     = make_uint4(lo0[0], lo0[1], lo0[2], lo0[3]);
        *(uint4*)(p0 + 8) = make_uint4(hi0[0], hi0[1], hi0[2], hi0[3]);
        unsigned* p1 = out + (size_t)(r0 + 8) * DKH + 16*tg + 4*wn;
        *(uint4*)(p1)     = make_uint4(lo1[0], lo1[1], lo1[2], lo1[3]);
        *(uint4*)(p1 + 8) = make_uint4(hi1[0], hi1[1], hi1[2], hi1[3]);
    }
}

// ============================================================================
// Kernel 1a: Q projection (reads input2). Scale = 1/8 * log2(e)  (exp2 domain).
// ============================================================================
__global__ __launch_bounds__(256) void proj_q_kernel(
    const float* __restrict__ in2,
    const float* __restrict__ Wq, const float* __restrict__ bq)
{
    __shared__ unsigned As[128*36];
    __shared__ unsigned Bs[32*72];

    const int tid = threadIdx.x;
    const int lane = tid & 31, wid = tid >> 5;
    const int g = lane >> 2, tg = lane & 3;
    const int wm = wid & 3, wn = wid >> 2;
    const int row0 = blockIdx.x * 128;

    float acc[2][4][4];
    #pragma unroll
    for (int i = 0; i < 2; i++)
        #pragma unroll
        for (int j = 0; j < 4; j++)
            #pragma unroll
            for (int e = 0; e < 4; e++) acc[i][j][e] = 0.f;

    for (int kc = 0; kc < EMB; kc += 32) {
        #pragma unroll
        for (int i = 0; i < 4; i++) {
            int idx = tid + i*256;
            int r = idx >> 3, c = (idx & 7) * 4;
            float4 v = *(const float4*)(in2 + (size_t)(row0 + r)*EMB + kc + c);
            *(uint4*)(As + r*36 + c) =
                make_uint4(f2tf(v.x), f2tf(v.y), f2tf(v.z), f2tf(v.w));
        }
        #pragma unroll
        for (int i = 0; i < 2; i++) {
            int idx = tid + i*256;
            int r = idx >> 4, c = (idx & 15) * 4;
            float4 v = *(const float4*)(Wq + (size_t)(kc + r)*DKH + c);
            *(uint4*)(Bs + r*72 + c) =
                make_uint4(f2tf(v.x), f2tf(v.y), f2tf(v.z), f2tf(v.w));
        }
        __syncthreads();

        #pragma unroll
        for (int ks = 0; ks < 4; ks++) {
            unsigned a[2][4];
            #pragma unroll
            for (int i = 0; i < 2; i++) {
                const unsigned* ap = As + (wm*32 + i*16 + g)*36 + ks*8 + tg;
                a[i][0] = ap[0]; a[i][1] = ap[8*36];
                a[i][2] = ap[4]; a[i][3] = ap[8*36 + 4];
            }
            unsigned bf[4][2];
            #pragma unroll
            for (int j = 0; j < 4; j++) {
                const unsigned* bp = Bs + (ks*8 + tg)*72 + wn*32 + j*8 + g;
                bf[j][0] = bp[0]; bf[j][1] = bp[4*72];
            }
            #pragma unroll
            for (int i = 0; i < 2; i++)
                #pragma unroll
                for (int j = 0; j < 4; j++)
                    mma8(acc[i][j], a[i][0], a[i][1], a[i][2], a[i][3],
                         bf[j][0], bf[j][1]);
        }
        __syncthreads();
    }
    const float QSCALE = 0.125f * 1.44269504088896340736f;  // 1/sqrt(dk) * log2(e)
    store_proj(g_Q, acc, bq, QSCALE, row0, wm, wn, g, tg);
}

// ============================================================================
// Kernel 1b: fused K+V projection (reads input1 ONCE, shared A tile).
// ============================================================================
__global__ __launch_bounds__(256) void proj_kv_kernel(
    const float* __restrict__ in1,
    const float* __restrict__ Wk, const float* __restrict__ bk,
    const float* __restrict__ Wv, const float* __restrict__ bv)
{
    __shared__ unsigned As[128*36];
    __shared__ unsigned Bk[32*72];
    __shared__ unsigned Bv[32*72];

    const int tid = threadIdx.x;
    const int lane = tid & 31, wid = tid >> 5;
    const int g = lane >> 2, tg = lane & 3;
    const int wm = wid & 3, wn = wid >> 2;
    const int row0 = blockIdx.x * 128;

    float ak[2][4][4], av[2][4][4];
    #pragma unroll
    for (int i = 0; i < 2; i++)
        #pragma unroll
        for (int j = 0; j < 4; j++)
            #pragma unroll
            for (int e = 0; e < 4; e++) { ak[i][j][e] = 0.f; av[i][j][e] = 0.f; }

    for (int kc = 0; kc < EMB; kc += 32) {
        #pragma unroll
        for (int i = 0; i < 4; i++) {
            int idx = tid + i*256;
            int r = idx >> 3, c = (idx & 7) * 4;
            float4 v = *(const float4*)(in1 + (size_t)(row0 + r)*EMB + kc + c);
            *(uint4*)(As + r*36 + c) =
                make_uint4(f2tf(v.x), f2tf(v.y), f2tf(v.z), f2tf(v.w));
        }
        #pragma unroll
        for (int i = 0; i < 2; i++) {
            int idx = tid + i*256;
            int r = idx >> 4, c = (idx & 15) * 4;
            float4 vk = *(const float4*)(Wk + (size_t)(kc + r)*DKH + c);
            *(uint4*)(Bk + r*72 + c) =
                make_uint4(f2tf(vk.x), f2tf(vk.y), f2tf(vk.z), f2tf(vk.w));
            float4 vv = *(const float4*)(Wv + (size_t)(kc + r)*DKH + c);
            *(uint4*)(Bv + r*72 + c) =
                make_uint4(f2tf(vv.x), f2tf(vv.y), f2tf(vv.z), f2tf(vv.w));
        }
        __syncthreads();

        #pragma unroll
        for (int ks = 0; ks < 4; ks++) {
            unsigned a[2][4];
            #pragma unroll
            for (int i = 0; i < 2; i++) {
                const unsigned* ap = As + (wm*32 + i*16 + g)*36 + ks*8 + tg;
                a[i][0] = ap[0]; a[i][1] = ap[8*36];
                a[i][2] = ap[4]; a[i][3] = ap[8*36 + 4];
            }
            unsigned fk[4][2], fv[4][2];
            #pragma unroll
            for (int j = 0; j < 4; j++) {
                const unsigned* kp = Bk + (ks*8 + tg)*72 + wn*32 + j*8 + g;
                fk[j][0] = kp[0]; fk[j][1] = kp[4*72];
                const unsigned* vp = Bv + (ks*8 + tg)*72 + wn*32 + j*8 + g;
                fv[j][0] = vp[0]; fv[j][1] = vp[4*72];
            }
            #pragma unroll
            for (int i = 0; i < 2; i++)
                #pragma unroll
                for (int j = 0; j < 4; j++) {
                    mma8(ak[i][j], a[i][0], a[i][1], a[i][2], a[i][3],
                         fk[j][0], fk[j][1]);
                    mma8(av[i][j], a[i][0], a[i][1], a[i][2], a[i][3],
                         fv[j][0], fv[j][1]);
                }
        }
        __syncthreads();
    }
    store_proj(g_K, ak, bk, 1.0f, row0, wm, wn, g, tg);
    store_proj(g_V, av, bv, 1.0f, row0, wm, wn, g, tg);
}

// ============================================================================
// Kernel 2: flash attention, NO split.  grid = (SL/64, NB), 128 threads
// (4 warps x 16 q-rows = 64 q-rows/CTA).  256 CTAs cover all 148 SMs, and
// no launch-bounds reg cap -> no spills; ~3 CTAs/SM co-resident.
// All frag gathers are LDS.128 thanks to the d-transposed tf32 layout.
// ============================================================================
#define SK 68
#define SMEM_ATTN ((64*SK + 64*SK + 4*16*SK) * 4)   // 52224 B

__global__ __launch_bounds__(128) void attn_kernel(float* __restrict__ out)
{
    extern __shared__ unsigned smem[];
    unsigned* Ks = smem;                 // [64][SK]
    unsigned* Vs = smem + 64*SK;         // [64][SK]
    unsigned* Ps = smem + 128*SK;        // [4 warps][16][SK], key-transposed

    const int tid = threadIdx.x;
    const int lane = tid & 31, wid = tid >> 5;
    const int g = lane >> 2, tg = lane & 3;
    const int b = blockIdx.y;

    const unsigned* Qg = g_Q + ((size_t)b*SL + blockIdx.x*64 + wid*16) * DKH;
    const unsigned* Kg = g_K + (size_t)b*SL*DKH;
    const unsigned* Vg = g_V + (size_t)b*SL*DKH;
    unsigned* Pw = Ps + wid*16*SK;

    // ---- Q frags: loaded ONCE, live in registers (8 LDG.128 x2 rows) ----
    unsigned ql0[8], ql1[8], qh0[8], qh1[8];
    {
        const unsigned* q0 = Qg + (size_t)g * DKH;
        const unsigned* q1 = Qg + (size_t)(g + 8) * DKH;
        *(uint4*)(ql0)     = *(const uint4*)(q0 + tg*8);
        *(uint4*)(ql0 + 4) = *(const uint4*)(q0 + tg*8 + 4);
        *(uint4*)(qh0)     = *(const uint4*)(q0 + tg*8 + 32);
        *(uint4*)(qh0 + 4) = *(const uint4*)(q0 + tg*8 + 36);
        *(uint4*)(ql1)     = *(const uint4*)(q1 + tg*8);
        *(uint4*)(ql1 + 4) = *(const uint4*)(q1 + tg*8 + 4);
        *(uint4*)(qh1)     = *(const uint4*)(q1 + tg*8 + 32);
        *(uint4*)(qh1 + 4) = *(const uint4*)(q1 + tg*8 + 36);
    }

    float o[8][4];
    #pragma unroll
    for (int dt = 0; dt < 8; dt++)
        #pragma unroll
        for (int e = 0; e < 4; e++) o[dt][e] = 0.f;

    float m0 = -3.402823466e38f, m1 = -3.402823466e38f;
    float l0 = 0.f, l1 = 0.f;

    for (int k0 = 0; k0 < SL; k0 += 64) {
        // ---- tile load: already tf32 + d-transposed, pure uint4 copy ----
        #pragma unroll
        for (int i = 0; i < 8; i++) {
            int idx = tid + i*128;           // 0..1023
            int r = idx >> 4, cu = (idx & 15) * 4;
            *(uint4*)(Ks + r*SK + cu) = *(const uint4*)(Kg + (size_t)(k0+r)*DKH + cu);
            *(uint4*)(Vs + r*SK + cu) = *(const uint4*)(Vg + (size_t)(k0+r)*DKH + cu);
        }
        __syncthreads();

        // ---- S = Q @ K^T  (16 rows x 64 keys per warp) ----
        float s[8][4];
        #pragma unroll
        for (int nt = 0; nt < 8; nt++) {
            const unsigned* kb = Ks + (nt*8 + g)*SK + tg*8;
            unsigned kl[8], kh[8];
            *(uint4*)(kl)     = *(const uint4*)(kb);
            *(uint4*)(kl + 4) = *(const uint4*)(kb + 4);
            *(uint4*)(kh)     = *(const uint4*)(kb + 32);
            *(uint4*)(kh + 4) = *(const uint4*)(kb + 36);
            s[nt][0] = s[nt][1] = s[nt][2] = s[nt][3] = 0.f;
            #pragma unroll
            for (int dk = 0; dk < 8; dk++)
                mma8(s[nt], ql0[dk], ql1[dk], qh0[dk], qh1[dk], kl[dk], kh[dk]);
        }

        // ---- online softmax (log2 domain; scale pre-folded into Q) ----
        float mx0 = m0, mx1 = m1;
        #pragma unroll
        for (int nt = 0; nt < 8; nt++) {
            mx0 = fmaxf(mx0, fmaxf(s[nt][0], s[nt][1]));
            mx1 = fmaxf(mx1, fmaxf(s[nt][2], s[nt][3]));
        }
        mx0 = fmaxf(mx0, __shfl_xor_sync(0xffffffffu, mx0, 1));
        mx0 = fmaxf(mx0, __shfl_xor_sync(0xffffffffu, mx0, 2));
        mx1 = fmaxf(mx1, __shfl_xor_sync(0xffffffffu, mx1, 1));
        mx1 = fmaxf(mx1, __shfl_xor_sync(0xffffffffu, mx1, 2));

        float f0 = ex2(m0 - mx0);
        float f1 = ex2(m1 - mx1);

        float sum0 = 0.f, sum1 = 0.f;
        #pragma unroll
        for (int nt = 0; nt < 8; nt++) {
            s[nt][0] = ex2(s[nt][0] - mx0);
            s[nt][1] = ex2(s[nt][1] - mx0);
            s[nt][2] = ex2(s[nt][2] - mx1);
            s[nt][3] = ex2(s[nt][3] - mx1);
            sum0 += s[nt][0] + s[nt][1];
            sum1 += s[nt][2] + s[nt][3];
        }
        sum0 += __shfl_xor_sync(0xffffffffu, sum0, 1);
        sum0 += __shfl_xor_sync(0xffffffffu, sum0, 2);
        sum1 += __shfl_xor_sync(0xffffffffu, sum1, 1);
        sum1 += __shfl_xor_sync(0xffffffffu, sum1, 2);

        l0 = l0 * f0 + sum0;
        l1 = l1 * f1 + sum1;
        m0 = mx0; m1 = mx1;

        #pragma unroll
        for (int dt = 0; dt < 8; dt++) {
            o[dt][0] *= f0; o[dt][1] *= f0;
            o[dt][2] *= f1; o[dt][3] *= f1;
        }

        // ---- P -> smem, key-transposed (STS.128 x8) ----
        {
            unsigned* p0 = Pw + g*SK + 16*tg;
            *(uint4*)(p0)      = make_uint4(f2tf(s[0][0]), f2tf(s[1][0]), f2tf(s[2][0]), f2tf(s[3][0]));
            *(uint4*)(p0 + 4)  = make_uint4(f2tf(s[4][0]), f2tf(s[5][0]), f2tf(s[6][0]), f2tf(s[7][0]));
            *(uint4*)(p0 + 8)  = make_uint4(f2tf(s[0][1]), f2tf(s[1][1]), f2tf(s[2][1]), f2tf(s[3][1]));
            *(uint4*)(p0 + 12) = make_uint4(f2tf(s[4][1]), f2tf(s[5][1]), f2tf(s[6][1]), f2tf(s[7][1]));
            unsigned* p1 = Pw + (g + 8)*SK + 16*tg;
            *(uint4*)(p1)      = make_uint4(f2tf(s[0][2]), f2tf(s[1][2]), f2tf(s[2][2]), f2tf(s[3][2]));
            *(uint4*)(p1 + 4)  = make_uint4(f2tf(s[4][2]), f2tf(s[5][2]), f2tf(s[6][2]), f2tf(s[7][2]));
            *(uint4*)(p1 + 8)  = make_uint4(f2tf(s[0][3]), f2tf(s[1][3]), f2tf(s[2][3]), f2tf(s[3][3]));
            *(uint4*)(p1 + 12) = make_uint4(f2tf(s[4][3]), f2tf(s[5][3]), f2tf(s[6][3]), f2tf(s[7][3]));
        }
        __syncwarp();

        // ---- P frags (all 8 k-steps, 8x LDS.128) ----
        unsigned pl0[8], pl1[8], ph0[8], ph1[8];
        {
            const unsigned* pr0 = Pw + g*SK;
            const unsigned* pr1 = Pw + (g + 8)*SK;
            *(uint4*)(pl0)     = *(const uint4*)(pr0 + tg*8);
            *(uint4*)(pl0 + 4) = *(const uint4*)(pr0 + tg*8 + 4);
            *(uint4*)(ph0)     = *(const uint4*)(pr0 + tg*8 + 32);
            *(uint4*)(ph0 + 4) = *(const uint4*)(pr0 + tg*8 + 36);
            *(uint4*)(pl1)     = *(const uint4*)(pr1 + tg*8);
            *(uint4*)(pl1 + 4) = *(const uint4*)(pr1 + tg*8 + 4);
            *(uint4*)(ph1)     = *(const uint4*)(pr1 + tg*8 + 32);
            *(uint4*)(ph1 + 4) = *(const uint4*)(pr1 + tg*8 + 36);
        }

        // ---- O += P @ V ----
        #pragma unroll
        for (int kk = 0; kk < 8; kk++) {
            const unsigned* vb0 = Vs + (kk*8 + tg)*SK + g*8;
            const unsigned* vb1 = vb0 + 4*SK;
            unsigned vl[8], vh[8];
            *(uint4*)(vl)     = *(const uint4*)(vb0);
            *(uint4*)(vl + 4) = *(const uint4*)(vb0 + 4);
            *(uint4*)(vh)     = *(const uint4*)(vb1);
            *(uint4*)(vh + 4) = *(const uint4*)(vb1 + 4);
            #pragma unroll
            for (int dt = 0; dt < 8; dt++)
                mma8(o[dt], pl0[kk], pl1[kk], ph0[kk], ph1[kk], vl[dt], vh[dt]);
        }
        __syncthreads();
    }

    // ---- epilogue: divide by l, direct store ----
    float inv0 = 1.f / l0, inv1 = 1.f / l1;
    float* og = out + ((size_t)b*SL + blockIdx.x*64 + wid*16) * DKH;
    #pragma unroll
    for (int dt = 0; dt < 8; dt++) {
        int c = dt*8 + 2*tg;
        float2 v0 = make_float2(o[dt][0]*inv0, o[dt][1]*inv0);
        float2 v1 = make_float2(o[dt][2]*inv1, o[dt][3]*inv1);
        *(float2*)(og + (size_t)g*DKH + c)       = v0;
        *(float2*)(og + (size_t)(g + 8)*DKH + c) = v1;
    }
}

// ============================================================================
extern "C" void kernel_launch(void* const* d_in, const int* in_sizes, int n_in,
                              void* d_out, int out_size)
{
    const float* in1 = (const float*)d_in[0];
    const float* in2 = (const float*)d_in[1];
    const float* Wq  = (const float*)d_in[2];
    const float* bq  = (const float*)d_in[3];
    const float* Wk  = (const float*)d_in[4];
    const float* bk  = (const float*)d_in[5];
    const float* Wv  = (const float*)d_in[6];
    const float* bv  = (const float*)d_in[7];
    float* out = (float*)d_out;

    cudaFuncSetAttribute(attn_kernel,
                         cudaFuncAttributeMaxDynamicSharedMemorySize, SMEM_ATTN);

    proj_q_kernel <<<MTOT/128, 256>>>(in2, Wq, bq);
    proj_kv_kernel<<<MTOT/128, 256>>>(in1, Wk, bk, Wv, bv);
    attn_kernel<<<dim3(SL/64, NB), 128, SMEM_ATTN>>>(out);
}

// round 12
// speedup vs baseline: 1.2407x; 1.2166x over previous
#include <cuda_runtime.h>

#define EMB 1024
#define DKH 64
#define NB 4
#define SL 4096
#define MTOT (NB*SL)

// ---------------- scratch (no allocations allowed) ----------------
// Q/K/V stored as tf32 bits, d-transposed within each 64-wide row:
//   element (row, d) lives at word  row*64 + (d%8)*8 + d/8
__device__ unsigned g_Q[MTOT*DKH];
__device__ unsigned g_K[MTOT*DKH];
__device__ unsigned g_V[MTOT*DKH];

// ---------------- helpers ----------------
__device__ __forceinline__ unsigned f2tf(float f){
    unsigned u; asm("cvt.rna.tf32.f32 %0, %1;" : "=r"(u) : "f"(f)); return u;
}
__device__ __forceinline__ float ex2(float x){
    float y; asm("ex2.approx.ftz.f32 %0, %1;" : "=f"(y) : "f"(x)); return y;
}
__device__ __forceinline__ void mma8(float* c,
        unsigned a0, unsigned a1, unsigned a2, unsigned a3,
        unsigned b0, unsigned b1){
    asm volatile(
        "mma.sync.aligned.m16n8k8.row.col.f32.tf32.tf32.f32 "
        "{%0,%1,%2,%3},{%4,%5,%6,%7},{%8,%9},{%0,%1,%2,%3};"
        : "+f"(c[0]), "+f"(c[1]), "+f"(c[2]), "+f"(c[3])
        : "r"(a0), "r"(a1), "r"(a2), "r"(a3), "r"(b0), "r"(b1));
}
__device__ __forceinline__ void cpa16(unsigned* s, const unsigned* g){
    asm volatile("cp.async.cg.shared.global [%0], [%1], 16;"
        :: "r"((unsigned)__cvta_generic_to_shared(s)), "l"(g));
}

// Epilogue store: bias + scale, tf32 convert, d-transposed layout (VALIDATED).
__device__ __forceinline__ void store_proj(unsigned* out, float acc[2][4][4],
        const float* __restrict__ bias, float scale,
        int row0, int wm, int wn, int g, int tg)
{
    #pragma unroll
    for (int i = 0; i < 2; i++) {
        int r0 = row0 + wm*32 + i*16 + g;
        unsigned lo0[4], hi0[4], lo1[4], hi1[4];
        #pragma unroll
        for (int j = 0; j < 4; j++) {
            int c = wn*32 + j*8 + 2*tg;
            float b0 = bias[c], b1 = bias[c+1];
            lo0[j] = f2tf((acc[i][j][0] + b0) * scale);
            hi0[j] = f2tf((acc[i][j][1] + b1) * scale);
            lo1[j] = f2tf((acc[i][j][2] + b0) * scale);
            hi1[j] = f2tf((acc[i][j][3] + b1) * scale);
        }
        unsigned* p0 = out + (size_t)r0 * DKH + 16*tg + 4*wn;
        *(uint4*)(p0)     = make_uint4(lo0[0], lo0[1], lo0[2], lo0[3]);
        *(uint4*)(p0 + 8) = make_uint4(hi0[0], hi0[1], hi0[2], hi0[3]);
        unsigned* p1 = out + (size_t)(r0 + 8) * DKH + 16*tg + 4*wn;
        *(uint4*)(p1)     = make_uint4(lo1[0], lo1[1], lo1[2], lo1[3]);
        *(uint4*)(p1 + 8) = make_uint4(hi1[0], hi1[1], hi1[2], hi1[3]);
    }
}

// ============================================================================
// Kernel 1: QKV projection, UN-fused: blockIdx.y = 0/1/2 -> Q/K/V.
// 384 CTAs (2/SM co-resident). Register-prefetch pipeline: next chunk's
// A/B tiles LDG'd into regs while current chunk's 32 mmas run from smem.
// ============================================================================
__global__ __launch_bounds__(256) void proj_kernel(
    const float* __restrict__ in1, const float* __restrict__ in2,
    const float* __restrict__ Wq, const float* __restrict__ bq,
    const float* __restrict__ Wk, const float* __restrict__ bk,
    const float* __restrict__ Wv, const float* __restrict__ bv)
{
    __shared__ unsigned As[128*36];
    __shared__ unsigned Bs[32*72];

    const int tid = threadIdx.x;
    const int lane = tid & 31, wid = tid >> 5;
    const int g = lane >> 2, tg = lane & 3;
    const int wm = wid & 3, wn = wid >> 2;
    const int row0 = blockIdx.x * 128;

    const int sel = blockIdx.y;
    const float* A    = (sel == 0) ? in2 : in1;
    const float* W    = (sel == 0) ? Wq : (sel == 1 ? Wk : Wv);
    const float* bias = (sel == 0) ? bq : (sel == 1 ? bk : bv);
    unsigned* out = (sel == 0) ? g_Q : (sel == 1 ? g_K : g_V);
    // Q carries softmax scale * log2(e) for the exp2-domain softmax.
    const float scale = (sel == 0) ? 0.125f * 1.44269504088896340736f : 1.0f;

    // per-thread load coordinates
    const int ar = tid >> 3,  ac = (tid & 7) * 4;     // + i*32 rows
    const int br = tid >> 4,  bc = (tid & 15) * 4;    // + i*16 rows

    float acc[2][4][4];
    #pragma unroll
    for (int i = 0; i < 2; i++)
        #pragma unroll
        for (int j = 0; j < 4; j++)
            #pragma unroll
            for (int e = 0; e < 4; e++) acc[i][j][e] = 0.f;

    // ---- prefetch chunk 0 into registers ----
    float4 Ar[4], Br[2];
    #pragma unroll
    for (int i = 0; i < 4; i++)
        Ar[i] = *(const float4*)(A + (size_t)(row0 + ar + i*32)*EMB + ac);
    #pragma unroll
    for (int i = 0; i < 2; i++)
        Br[i] = *(const float4*)(W + (size_t)(br + i*16)*DKH + bc);

    for (int kc = 0; kc < EMB; kc += 32) {
        // ---- commit prefetched regs to smem (tf32 convert here) ----
        #pragma unroll
        for (int i = 0; i < 4; i++)
            *(uint4*)(As + (ar + i*32)*36 + ac) =
                make_uint4(f2tf(Ar[i].x), f2tf(Ar[i].y), f2tf(Ar[i].z), f2tf(Ar[i].w));
        #pragma unroll
        for (int i = 0; i < 2; i++)
            *(uint4*)(Bs + (br + i*16)*72 + bc) =
                make_uint4(f2tf(Br[i].x), f2tf(Br[i].y), f2tf(Br[i].z), f2tf(Br[i].w));
        __syncthreads();

        // ---- issue prefetch for next chunk (hidden behind mma compute) ----
        if (kc + 32 < EMB) {
            #pragma unroll
            for (int i = 0; i < 4; i++)
                Ar[i] = *(const float4*)(A + (size_t)(row0 + ar + i*32)*EMB + kc + 32 + ac);
            #pragma unroll
            for (int i = 0; i < 2; i++)
                Br[i] = *(const float4*)(W + (size_t)(kc + 32 + br + i*16)*DKH + bc);
        }

        // ---- compute: 4 k-steps x 8 mmas ----
        #pragma unroll
        for (int ks = 0; ks < 4; ks++) {
            unsigned a[2][4];
            #pragma unroll
            for (int i = 0; i < 2; i++) {
                const unsigned* ap = As + (wm*32 + i*16 + g)*36 + ks*8 + tg;
                a[i][0] = ap[0]; a[i][1] = ap[8*36];
                a[i][2] = ap[4]; a[i][3] = ap[8*36 + 4];
            }
            unsigned bf[4][2];
            #pragma unroll
            for (int j = 0; j < 4; j++) {
                const unsigned* bp = Bs + (ks*8 + tg)*72 + wn*32 + j*8 + g;
                bf[j][0] = bp[0]; bf[j][1] = bp[4*72];
            }
            #pragma unroll
            for (int i = 0; i < 2; i++)
                #pragma unroll
                for (int j = 0; j < 4; j++)
                    mma8(acc[i][j], a[i][0], a[i][1], a[i][2], a[i][3],
                         bf[j][0], bf[j][1]);
        }
        __syncthreads();
    }
    store_proj(out, acc, bias, scale, row0, wm, wn, g, tg);
}

// ============================================================================
// Kernel 2: flash attention, cp.async double-buffered K/V tiles.
// grid = (SL/64, NB) = 256 CTAs, 128 threads (4 warps x 16 q-rows).
// smem: K0,V0,K1,V1 (tf32, stride 68) + per-warp P.  ~87KB -> 2 CTAs/SM.
// All frag gathers are LDS.128 (d-transposed layout, validated).
// ============================================================================
#define SK 68
#define TILE_WORDS (64*SK)
#define NT (SL/64)
#define SMEM_ATTN ((4*TILE_WORDS + 4*16*SK) * 4)   // 87040 B

__global__ __launch_bounds__(128) void attn_kernel(float* __restrict__ out)
{
    extern __shared__ unsigned smem[];
    unsigned* Ps = smem + 4*TILE_WORDS;            // [4 warps][16][SK]

    const int tid = threadIdx.x;
    const int lane = tid & 31, wid = tid >> 5;
    const int g = lane >> 2, tg = lane & 3;
    const int b = blockIdx.y;

    const unsigned* Qg = g_Q + ((size_t)b*SL + blockIdx.x*64 + wid*16) * DKH;
    const unsigned* Kg = g_K + (size_t)b*SL*DKH;
    const unsigned* Vg = g_V + (size_t)b*SL*DKH;
    unsigned* Pw = Ps + wid*16*SK;

    const int cr = tid >> 4, cc = (tid & 15) * 4;  // copy coords: + i*8 rows

    // ---- prologue: cp.async tile 0 into buffer 0 ----
    {
        unsigned* K0 = smem;
        unsigned* V0 = smem + TILE_WORDS;
        #pragma unroll
        for (int i = 0; i < 8; i++) {
            cpa16(K0 + (cr + i*8)*SK + cc, Kg + (size_t)(cr + i*8)*DKH + cc);
            cpa16(V0 + (cr + i*8)*SK + cc, Vg + (size_t)(cr + i*8)*DKH + cc);
        }
        asm volatile("cp.async.commit_group;");
    }

    // ---- Q frags: loaded ONCE, live in registers ----
    unsigned ql0[8], ql1[8], qh0[8], qh1[8];
    {
        const unsigned* q0 = Qg + (size_t)g * DKH;
        const unsigned* q1 = Qg + (size_t)(g + 8) * DKH;
        *(uint4*)(ql0)     = *(const uint4*)(q0 + tg*8);
        *(uint4*)(ql0 + 4) = *(const uint4*)(q0 + tg*8 + 4);
        *(uint4*)(qh0)     = *(const uint4*)(q0 + tg*8 + 32);
        *(uint4*)(qh0 + 4) = *(const uint4*)(q0 + tg*8 + 36);
        *(uint4*)(ql1)     = *(const uint4*)(q1 + tg*8);
        *(uint4*)(ql1 + 4) = *(const uint4*)(q1 + tg*8 + 4);
        *(uint4*)(qh1)     = *(const uint4*)(q1 + tg*8 + 32);
        *(uint4*)(qh1 + 4) = *(const uint4*)(q1 + tg*8 + 36);
    }

    float o[8][4];
    #pragma unroll
    for (int dt = 0; dt < 8; dt++)
        #pragma unroll
        for (int e = 0; e < 4; e++) o[dt][e] = 0.f;

    float m0 = -3.402823466e38f, m1 = -3.402823466e38f;
    float l0 = 0.f, l1 = 0.f;

    for (int t = 0; t < NT; t++) {
        unsigned* Ks = smem + (t & 1) * 2*TILE_WORDS;
        unsigned* Vs = Ks + TILE_WORDS;

        // ---- issue cp.async for tile t+1 into the other buffer ----
        if (t + 1 < NT) {
            unsigned* Kn = smem + ((t + 1) & 1) * 2*TILE_WORDS;
            unsigned* Vn = Kn + TILE_WORDS;
            const unsigned* Ksrc = Kg + (size_t)(t + 1)*64*DKH;
            const unsigned* Vsrc = Vg + (size_t)(t + 1)*64*DKH;
            #pragma unroll
            for (int i = 0; i < 8; i++) {
                cpa16(Kn + (cr + i*8)*SK + cc, Ksrc + (size_t)(cr + i*8)*DKH + cc);
                cpa16(Vn + (cr + i*8)*SK + cc, Vsrc + (size_t)(cr + i*8)*DKH + cc);
            }
            asm volatile("cp.async.commit_group;");
            asm volatile("cp.async.wait_group 1;");   // tile t complete
        } else {
            asm volatile("cp.async.wait_group 0;");
        }
        __syncthreads();

        // ---- S = Q @ K^T  (16 rows x 64 keys per warp) ----
        float s[8][4];
        #pragma unroll
        for (int nt = 0; nt < 8; nt++) {
            const unsigned* kb = Ks + (nt*8 + g)*SK + tg*8;
            unsigned kl[8], kh[8];
            *(uint4*)(kl)     = *(const uint4*)(kb);
            *(uint4*)(kl + 4) = *(const uint4*)(kb + 4);
            *(uint4*)(kh)     = *(const uint4*)(kb + 32);
            *(uint4*)(kh + 4) = *(const uint4*)(kb + 36);
            s[nt][0] = s[nt][1] = s[nt][2] = s[nt][3] = 0.f;
            #pragma unroll
            for (int dk = 0; dk < 8; dk++)
                mma8(s[nt], ql0[dk], ql1[dk], qh0[dk], qh1[dk], kl[dk], kh[dk]);
        }

        // ---- online softmax (exp2 domain; scale pre-folded into Q) ----
        float mx0 = m0, mx1 = m1;
        #pragma unroll
        for (int nt = 0; nt < 8; nt++) {
            mx0 = fmaxf(mx0, fmaxf(s[nt][0], s[nt][1]));
            mx1 = fmaxf(mx1, fmaxf(s[nt][2], s[nt][3]));
        }
        mx0 = fmaxf(mx0, __shfl_xor_sync(0xffffffffu, mx0, 1));
        mx0 = fmaxf(mx0, __shfl_xor_sync(0xffffffffu, mx0, 2));
        mx1 = fmaxf(mx1, __shfl_xor_sync(0xffffffffu, mx1, 1));
        mx1 = fmaxf(mx1, __shfl_xor_sync(0xffffffffu, mx1, 2));

        float f0 = ex2(m0 - mx0);
        float f1 = ex2(m1 - mx1);

        float sum0 = 0.f, sum1 = 0.f;
        #pragma unroll
        for (int nt = 0; nt < 8; nt++) {
            s[nt][0] = ex2(s[nt][0] - mx0);
            s[nt][1] = ex2(s[nt][1] - mx0);
            s[nt][2] = ex2(s[nt][2] - mx1);
            s[nt][3] = ex2(s[nt][3] - mx1);
            sum0 += s[nt][0] + s[nt][1];
            sum1 += s[nt][2] + s[nt][3];
        }
        sum0 += __shfl_xor_sync(0xffffffffu, sum0, 1);
        sum0 += __shfl_xor_sync(0xffffffffu, sum0, 2);
        sum1 += __shfl_xor_sync(0xffffffffu, sum1, 1);
        sum1 += __shfl_xor_sync(0xffffffffu, sum1, 2);

        l0 = l0 * f0 + sum0;
        l1 = l1 * f1 + sum1;
        m0 = mx0; m1 = mx1;

        #pragma unroll
        for (int dt = 0; dt < 8; dt++) {
            o[dt][0] *= f0; o[dt][1] *= f0;
            o[dt][2] *= f1; o[dt][3] *= f1;
        }

        // ---- P -> smem, key-transposed (STS.128 x8) ----
        {
            unsigned* p0 = Pw + g*SK + 16*tg;
            *(uint4*)(p0)      = make_uint4(f2tf(s[0][0]), f2tf(s[1][0]), f2tf(s[2][0]), f2tf(s[3][0]));
            *(uint4*)(p0 + 4)  = make_uint4(f2tf(s[4][0]), f2tf(s[5][0]), f2tf(s[6][0]), f2tf(s[7][0]));
            *(uint4*)(p0 + 8)  = make_uint4(f2tf(s[0][1]), f2tf(s[1][1]), f2tf(s[2][1]), f2tf(s[3][1]));
            *(uint4*)(p0 + 12) = make_uint4(f2tf(s[4][1]), f2tf(s[5][1]), f2tf(s[6][1]), f2tf(s[7][1]));
            unsigned* p1 = Pw + (g + 8)*SK + 16*tg;
            *(uint4*)(p1)      = make_uint4(f2tf(s[0][2]), f2tf(s[1][2]), f2tf(s[2][2]), f2tf(s[3][2]));
            *(uint4*)(p1 + 4)  = make_uint4(f2tf(s[4][2]), f2tf(s[5][2]), f2tf(s[6][2]), f2tf(s[7][2]));
            *(uint4*)(p1 + 8)  = make_uint4(f2tf(s[0][3]), f2tf(s[1][3]), f2tf(s[2][3]), f2tf(s[3][3]));
            *(uint4*)(p1 + 12) = make_uint4(f2tf(s[4][3]), f2tf(s[5][3]), f2tf(s[6][3]), f2tf(s[7][3]));
        }
        __syncwarp();

        // ---- P frags (all 8 k-steps, 8x LDS.128) ----
        unsigned pl0[8], pl1[8], ph0[8], ph1[8];
        {
            const unsigned* pr0 = Pw + g*SK;
            const unsigned* pr1 = Pw + (g + 8)*SK;
            *(uint4*)(pl0)     = *(const uint4*)(pr0 + tg*8);
            *(uint4*)(pl0 + 4) = *(const uint4*)(pr0 + tg*8 + 4);
            *(uint4*)(ph0)     = *(const uint4*)(pr0 + tg*8 + 32);
            *(uint4*)(ph0 + 4) = *(const uint4*)(pr0 + tg*8 + 36);
            *(uint4*)(pl1)     = *(const uint4*)(pr1 + tg*8);
            *(uint4*)(pl1 + 4) = *(const uint4*)(pr1 + tg*8 + 4);
            *(uint4*)(ph1)     = *(const uint4*)(pr1 + tg*8 + 32);
            *(uint4*)(ph1 + 4) = *(const uint4*)(pr1 + tg*8 + 36);
        }

        // ---- O += P @ V ----
        #pragma unroll
        for (int kk = 0; kk < 8; kk++) {
            const unsigned* vb0 = Vs + (kk*8 + tg)*SK + g*8;
            const unsigned* vb1 = vb0 + 4*SK;
            unsigned vl[8], vh[8];
            *(uint4*)(vl)     = *(const uint4*)(vb0);
            *(uint4*)(vl + 4) = *(const uint4*)(vb0 + 4);
            *(uint4*)(vh)     = *(const uint4*)(vb1);
            *(uint4*)(vh + 4) = *(const uint4*)(vb1 + 4);
            #pragma unroll
            for (int dt = 0; dt < 8; dt++)
                mma8(o[dt], pl0[kk], pl1[kk], ph0[kk], ph1[kk], vl[dt], vh[dt]);
        }
        __syncthreads();
    }

    // ---- epilogue: divide by l, direct store ----
    float inv0 = 1.f / l0, inv1 = 1.f / l1;
    float* og = out + ((size_t)b*SL + blockIdx.x*64 + wid*16) * DKH;
    #pragma unroll
    for (int dt = 0; dt < 8; dt++) {
        int c = dt*8 + 2*tg;
        float2 v0 = make_float2(o[dt][0]*inv0, o[dt][1]*inv0);
        float2 v1 = make_float2(o[dt][2]*inv1, o[dt][3]*inv1);
        *(float2*)(og + (size_t)g*DKH + c)       = v0;
        *(float2*)(og + (size_t)(g + 8)*DKH + c) = v1;
    }
}

// ============================================================================
extern "C" void kernel_launch(void* const* d_in, const int* in_sizes, int n_in,
                              void* d_out, int out_size)
{
    const float* in1 = (const float*)d_in[0];
    const float* in2 = (const float*)d_in[1];
    const float* Wq  = (const float*)d_in[2];
    const float* bq  = (const float*)d_in[3];
    const float* Wk  = (const float*)d_in[4];
    const float* bk  = (const float*)d_in[5];
    const float* Wv  = (const float*)d_in[6];
    const float* bv  = (const float*)d_in[7];
    float* out = (float*)d_out;

    cudaFuncSetAttribute(attn_kernel,
                         cudaFuncAttributeMaxDynamicSharedMemorySize, SMEM_ATTN);

    proj_kernel<<<dim3(MTOT/128, 3), 256>>>(in1, in2, Wq, bq, Wk, bk, Wv, bv);
    attn_kernel<<<dim3(SL/64, NB), 128, SMEM_ATTN>>>(out);
}

// round 13
// speedup vs baseline: 1.2583x; 1.0141x over previous
#include <cuda_runtime.h>

#define EMB 1024
#define DKH 64
#define NB 4
#define SL 4096
#define MTOT (NB*SL)
#define NSPLIT 2
#define TPS (SL/64/NSPLIT)     // key tiles per split = 32

// ---------------- scratch (no allocations allowed) ----------------
// Q/K/V stored as tf32 bits, d-transposed within each 64-wide row:
//   element (row, d) lives at word  row*64 + (d%8)*8 + d/8
__device__ unsigned g_Q[MTOT*DKH];
__device__ unsigned g_K[MTOT*DKH];
__device__ unsigned g_V[MTOT*DKH];
__device__ float    g_part[(size_t)NSPLIT*MTOT*DKH];  // unnormalized partial O
__device__ float    g_ml[(size_t)NSPLIT*MTOT*2];      // (m, l) per split per row

// ---------------- helpers ----------------
__device__ __forceinline__ unsigned f2tf(float f){
    unsigned u; asm("cvt.rna.tf32.f32 %0, %1;" : "=r"(u) : "f"(f)); return u;
}
__device__ __forceinline__ float ex2(float x){
    float y; asm("ex2.approx.ftz.f32 %0, %1;" : "=f"(y) : "f"(x)); return y;
}
__device__ __forceinline__ void mma8(float* c,
        unsigned a0, unsigned a1, unsigned a2, unsigned a3,
        unsigned b0, unsigned b1){
    asm volatile(
        "mma.sync.aligned.m16n8k8.row.col.f32.tf32.tf32.f32 "
        "{%0,%1,%2,%3},{%4,%5,%6,%7},{%8,%9},{%0,%1,%2,%3};"
        : "+f"(c[0]), "+f"(c[1]), "+f"(c[2]), "+f"(c[3])
        : "r"(a0), "r"(a1), "r"(a2), "r"(a3), "r"(b0), "r"(b1));
}
__device__ __forceinline__ void cpa16(unsigned* s, const unsigned* g){
    asm volatile("cp.async.cg.shared.global [%0], [%1], 16;"
        :: "r"((unsigned)__cvta_generic_to_shared(s)), "l"(g));
}

// Epilogue store: bias + scale, tf32 convert, d-transposed layout (VALIDATED).
__device__ __forceinline__ void store_proj(unsigned* out, float acc[2][4][4],
        const float* __restrict__ bias, float scale,
        int row0, int wm, int wn, int g, int tg)
{
    #pragma unroll
    for (int i = 0; i < 2; i++) {
        int r0 = row0 + wm*32 + i*16 + g;
        unsigned lo0[4], hi0[4], lo1[4], hi1[4];
        #pragma unroll
        for (int j = 0; j < 4; j++) {
            int c = wn*32 + j*8 + 2*tg;
            float b0 = bias[c], b1 = bias[c+1];
            lo0[j] = f2tf((acc[i][j][0] + b0) * scale);
            hi0[j] = f2tf((acc[i][j][1] + b1) * scale);
            lo1[j] = f2tf((acc[i][j][2] + b0) * scale);
            hi1[j] = f2tf((acc[i][j][3] + b1) * scale);
        }
        unsigned* p0 = out + (size_t)r0 * DKH + 16*tg + 4*wn;
        *(uint4*)(p0)     = make_uint4(lo0[0], lo0[1], lo0[2], lo0[3]);
        *(uint4*)(p0 + 8) = make_uint4(hi0[0], hi0[1], hi0[2], hi0[3]);
        unsigned* p1 = out + (size_t)(r0 + 8) * DKH + 16*tg + 4*wn;
        *(uint4*)(p1)     = make_uint4(lo1[0], lo1[1], lo1[2], lo1[3]);
        *(uint4*)(p1 + 8) = make_uint4(hi1[0], hi1[1], hi1[2], hi1[3]);
    }
}

// ============================================================================
// Kernel 1: QKV projection, UN-fused: blockIdx.y = 0/1/2 -> Q/K/V.
// 384 CTAs (2/SM). Register-prefetch pipeline (VALIDATED R12).
// ============================================================================
__global__ __launch_bounds__(256) void proj_kernel(
    const float* __restrict__ in1, const float* __restrict__ in2,
    const float* __restrict__ Wq, const float* __restrict__ bq,
    const float* __restrict__ Wk, const float* __restrict__ bk,
    const float* __restrict__ Wv, const float* __restrict__ bv)
{
    __shared__ unsigned As[128*36];
    __shared__ unsigned Bs[32*72];

    const int tid = threadIdx.x;
    const int lane = tid & 31, wid = tid >> 5;
    const int g = lane >> 2, tg = lane & 3;
    const int wm = wid & 3, wn = wid >> 2;
    const int row0 = blockIdx.x * 128;

    const int sel = blockIdx.y;
    const float* A    = (sel == 0) ? in2 : in1;
    const float* W    = (sel == 0) ? Wq : (sel == 1 ? Wk : Wv);
    const float* bias = (sel == 0) ? bq : (sel == 1 ? bk : bv);
    unsigned* out = (sel == 0) ? g_Q : (sel == 1 ? g_K : g_V);
    const float scale = (sel == 0) ? 0.125f * 1.44269504088896340736f : 1.0f;

    const int ar = tid >> 3,  ac = (tid & 7) * 4;
    const int br = tid >> 4,  bc = (tid & 15) * 4;

    float acc[2][4][4];
    #pragma unroll
    for (int i = 0; i < 2; i++)
        #pragma unroll
        for (int j = 0; j < 4; j++)
            #pragma unroll
            for (int e = 0; e < 4; e++) acc[i][j][e] = 0.f;

    float4 Ar[4], Br[2];
    #pragma unroll
    for (int i = 0; i < 4; i++)
        Ar[i] = *(const float4*)(A + (size_t)(row0 + ar + i*32)*EMB + ac);
    #pragma unroll
    for (int i = 0; i < 2; i++)
        Br[i] = *(const float4*)(W + (size_t)(br + i*16)*DKH + bc);

    for (int kc = 0; kc < EMB; kc += 32) {
        #pragma unroll
        for (int i = 0; i < 4; i++)
            *(uint4*)(As + (ar + i*32)*36 + ac) =
                make_uint4(f2tf(Ar[i].x), f2tf(Ar[i].y), f2tf(Ar[i].z), f2tf(Ar[i].w));
        #pragma unroll
        for (int i = 0; i < 2; i++)
            *(uint4*)(Bs + (br + i*16)*72 + bc) =
                make_uint4(f2tf(Br[i].x), f2tf(Br[i].y), f2tf(Br[i].z), f2tf(Br[i].w));
        __syncthreads();

        if (kc + 32 < EMB) {
            #pragma unroll
            for (int i = 0; i < 4; i++)
                Ar[i] = *(const float4*)(A + (size_t)(row0 + ar + i*32)*EMB + kc + 32 + ac);
            #pragma unroll
            for (int i = 0; i < 2; i++)
                Br[i] = *(const float4*)(W + (size_t)(kc + 32 + br + i*16)*DKH + bc);
        }

        #pragma unroll
        for (int ks = 0; ks < 4; ks++) {
            unsigned a[2][4];
            #pragma unroll
            for (int i = 0; i < 2; i++) {
                const unsigned* ap = As + (wm*32 + i*16 + g)*36 + ks*8 + tg;
                a[i][0] = ap[0]; a[i][1] = ap[8*36];
                a[i][2] = ap[4]; a[i][3] = ap[8*36 + 4];
            }
            unsigned bf[4][2];
            #pragma unroll
            for (int j = 0; j < 4; j++) {
                const unsigned* bp = Bs + (ks*8 + tg)*72 + wn*32 + j*8 + g;
                bf[j][0] = bp[0]; bf[j][1] = bp[4*72];
            }
            #pragma unroll
            for (int i = 0; i < 2; i++)
                #pragma unroll
                for (int j = 0; j < 4; j++)
                    mma8(acc[i][j], a[i][0], a[i][1], a[i][2], a[i][3],
                         bf[j][0], bf[j][1]);
        }
        __syncthreads();
    }
    store_proj(out, acc, bias, scale, row0, wm, wn, g, tg);
}

// ============================================================================
// Kernel 2: flash attention, split-K=2.
// grid = (SL/64, NB, NSPLIT) = 512 CTAs, 128 threads (4 warps x 16 q-rows).
// smem: K0,K1 (double-buffered), V (single), P = 69632B -> 3 CTAs/SM.
// Pipeline: V(t) + K(t+1) stream via cp.async while S(t)/softmax compute.
// ============================================================================
#define SK 68
#define KTW (64*SK)                               // one tile in words
#define SMEM_ATTN ((3*KTW + 4*16*SK) * 4)         // 69632 B

__global__ __launch_bounds__(128) void attn_kernel()
{
    extern __shared__ unsigned smem[];
    unsigned* Vs = smem + 2*KTW;                  // single V buffer
    unsigned* Ps = smem + 3*KTW;                  // [4 warps][16][SK]

    const int tid = threadIdx.x;
    const int lane = tid & 31, wid = tid >> 5;
    const int g = lane >> 2, tg = lane & 3;
    const int b = blockIdx.y;
    const int split = blockIdx.z;

    const unsigned* Qg = g_Q + ((size_t)b*SL + blockIdx.x*64 + wid*16) * DKH;
    const unsigned* Kg = g_K + ((size_t)b*SL + split*(SL/NSPLIT)) * DKH;
    const unsigned* Vg = g_V + ((size_t)b*SL + split*(SL/NSPLIT)) * DKH;
    unsigned* Pw = Ps + wid*16*SK;

    const int cr = tid >> 4, cc = (tid & 15) * 4;  // copy coords: + i*8 rows

    // ---- prologue: K tile 0 -> buffer 0 ----
    #pragma unroll
    for (int i = 0; i < 8; i++)
        cpa16(smem + (cr + i*8)*SK + cc, Kg + (size_t)(cr + i*8)*DKH + cc);
    asm volatile("cp.async.commit_group;");

    // ---- Q frags: loaded ONCE, live in registers ----
    unsigned ql0[8], ql1[8], qh0[8], qh1[8];
    {
        const unsigned* q0 = Qg + (size_t)g * DKH;
        const unsigned* q1 = Qg + (size_t)(g + 8) * DKH;
        *(uint4*)(ql0)     = *(const uint4*)(q0 + tg*8);
        *(uint4*)(ql0 + 4) = *(const uint4*)(q0 + tg*8 + 4);
        *(uint4*)(qh0)     = *(const uint4*)(q0 + tg*8 + 32);
        *(uint4*)(qh0 + 4) = *(const uint4*)(q0 + tg*8 + 36);
        *(uint4*)(ql1)     = *(const uint4*)(q1 + tg*8);
        *(uint4*)(ql1 + 4) = *(const uint4*)(q1 + tg*8 + 4);
        *(uint4*)(qh1)     = *(const uint4*)(q1 + tg*8 + 32);
        *(uint4*)(qh1 + 4) = *(const uint4*)(q1 + tg*8 + 36);
    }

    float o[8][4];
    #pragma unroll
    for (int dt = 0; dt < 8; dt++)
        #pragma unroll
        for (int e = 0; e < 4; e++) o[dt][e] = 0.f;

    float m0 = -3.402823466e38f, m1 = -3.402823466e38f;
    float l0 = 0.f, l1 = 0.f;

    for (int t = 0; t < TPS; t++) {
        unsigned* Ks = smem + (t & 1) * KTW;
        const bool more = (t + 1 < TPS);

        // ---- stream V(t) into the single V buffer (free: barrier at loop end) ----
        {
            const unsigned* Vsrc = Vg + (size_t)t*64*DKH;
            #pragma unroll
            for (int i = 0; i < 8; i++)
                cpa16(Vs + (cr + i*8)*SK + cc, Vsrc + (size_t)(cr + i*8)*DKH + cc);
            asm volatile("cp.async.commit_group;");
        }
        // ---- stream K(t+1) into the other K buffer ----
        if (more) {
            unsigned* Kn = smem + ((t + 1) & 1) * KTW;
            const unsigned* Ksrc = Kg + (size_t)(t + 1)*64*DKH;
            #pragma unroll
            for (int i = 0; i < 8; i++)
                cpa16(Kn + (cr + i*8)*SK + cc, Ksrc + (size_t)(cr + i*8)*DKH + cc);
            asm volatile("cp.async.commit_group;");
            asm volatile("cp.async.wait_group 2;");   // K(t) complete
        } else {
            asm volatile("cp.async.wait_group 1;");   // K(t) complete
        }
        __syncthreads();

        // ---- S = Q @ K^T  (16 rows x 64 keys per warp) ----
        float s[8][4];
        #pragma unroll
        for (int nt = 0; nt < 8; nt++) {
            const unsigned* kb = Ks + (nt*8 + g)*SK + tg*8;
            unsigned kl[8], kh[8];
            *(uint4*)(kl)     = *(const uint4*)(kb);
            *(uint4*)(kl + 4) = *(const uint4*)(kb + 4);
            *(uint4*)(kh)     = *(const uint4*)(kb + 32);
            *(uint4*)(kh + 4) = *(const uint4*)(kb + 36);
            s[nt][0] = s[nt][1] = s[nt][2] = s[nt][3] = 0.f;
            #pragma unroll
            for (int dk = 0; dk < 8; dk++)
                mma8(s[nt], ql0[dk], ql1[dk], qh0[dk], qh1[dk], kl[dk], kh[dk]);
        }

        // ---- online softmax (exp2 domain; scale pre-folded into Q) ----
        float mx0 = m0, mx1 = m1;
        #pragma unroll
        for (int nt = 0; nt < 8; nt++) {
            mx0 = fmaxf(mx0, fmaxf(s[nt][0], s[nt][1]));
            mx1 = fmaxf(mx1, fmaxf(s[nt][2], s[nt][3]));
        }
        mx0 = fmaxf(mx0, __shfl_xor_sync(0xffffffffu, mx0, 1));
        mx0 = fmaxf(mx0, __shfl_xor_sync(0xffffffffu, mx0, 2));
        mx1 = fmaxf(mx1, __shfl_xor_sync(0xffffffffu, mx1, 1));
        mx1 = fmaxf(mx1, __shfl_xor_sync(0xffffffffu, mx1, 2));

        float f0 = ex2(m0 - mx0);
        float f1 = ex2(m1 - mx1);

        float sum0 = 0.f, sum1 = 0.f;
        #pragma unroll
        for (int nt = 0; nt < 8; nt++) {
            s[nt][0] = ex2(s[nt][0] - mx0);
            s[nt][1] = ex2(s[nt][1] - mx0);
            s[nt][2] = ex2(s[nt][2] - mx1);
            s[nt][3] = ex2(s[nt][3] - mx1);
            sum0 += s[nt][0] + s[nt][1];
            sum1 += s[nt][2] + s[nt][3];
        }
        sum0 += __shfl_xor_sync(0xffffffffu, sum0, 1);
        sum0 += __shfl_xor_sync(0xffffffffu, sum0, 2);
        sum1 += __shfl_xor_sync(0xffffffffu, sum1, 1);
        sum1 += __shfl_xor_sync(0xffffffffu, sum1, 2);

        l0 = l0 * f0 + sum0;
        l1 = l1 * f1 + sum1;
        m0 = mx0; m1 = mx1;

        #pragma unroll
        for (int dt = 0; dt < 8; dt++) {
            o[dt][0] *= f0; o[dt][1] *= f0;
            o[dt][2] *= f1; o[dt][3] *= f1;
        }

        // ---- P -> smem, key-transposed (STS.128 x8) ----
        {
            unsigned* p0 = Pw + g*SK + 16*tg;
            *(uint4*)(p0)      = make_uint4(f2tf(s[0][0]), f2tf(s[1][0]), f2tf(s[2][0]), f2tf(s[3][0]));
            *(uint4*)(p0 + 4)  = make_uint4(f2tf(s[4][0]), f2tf(s[5][0]), f2tf(s[6][0]), f2tf(s[7][0]));
            *(uint4*)(p0 + 8)  = make_uint4(f2tf(s[0][1]), f2tf(s[1][1]), f2tf(s[2][1]), f2tf(s[3][1]));
            *(uint4*)(p0 + 12) = make_uint4(f2tf(s[4][1]), f2tf(s[5][1]), f2tf(s[6][1]), f2tf(s[7][1]));
            unsigned* p1 = Pw + (g + 8)*SK + 16*tg;
            *(uint4*)(p1)      = make_uint4(f2tf(s[0][2]), f2tf(s[1][2]), f2tf(s[2][2]), f2tf(s[3][2]));
            *(uint4*)(p1 + 4)  = make_uint4(f2tf(s[4][2]), f2tf(s[5][2]), f2tf(s[6][2]), f2tf(s[7][2]));
            *(uint4*)(p1 + 8)  = make_uint4(f2tf(s[0][3]), f2tf(s[1][3]), f2tf(s[2][3]), f2tf(s[3][3]));
            *(uint4*)(p1 + 12) = make_uint4(f2tf(s[4][3]), f2tf(s[5][3]), f2tf(s[6][3]), f2tf(s[7][3]));
        }
        __syncwarp();

        // ---- P frags (all 8 k-steps, 8x LDS.128) ----
        unsigned pl0[8], pl1[8], ph0[8], ph1[8];
        {
            const unsigned* pr0 = Pw + g*SK;
            const unsigned* pr1 = Pw + (g + 8)*SK;
            *(uint4*)(pl0)     = *(const uint4*)(pr0 + tg*8);
            *(uint4*)(pl0 + 4) = *(const uint4*)(pr0 + tg*8 + 4);
            *(uint4*)(ph0)     = *(const uint4*)(pr0 + tg*8 + 32);
            *(uint4*)(ph0 + 4) = *(const uint4*)(pr0 + tg*8 + 36);
            *(uint4*)(pl1)     = *(const uint4*)(pr1 + tg*8);
            *(uint4*)(pl1 + 4) = *(const uint4*)(pr1 + tg*8 + 4);
            *(uint4*)(ph1)     = *(const uint4*)(pr1 + tg*8 + 32);
            *(uint4*)(ph1 + 4) = *(const uint4*)(pr1 + tg*8 + 36);
        }

        // ---- wait V(t) complete (K(t+1) may still be in flight) ----
        if (more) asm volatile("cp.async.wait_group 1;");
        else      asm volatile("cp.async.wait_group 0;");
        __syncthreads();

        // ---- O += P @ V ----
        #pragma unroll
        for (int kk = 0; kk < 8; kk++) {
            const unsigned* vb0 = Vs + (kk*8 + tg)*SK + g*8;
            const unsigned* vb1 = vb0 + 4*SK;
            unsigned vl[8], vh[8];
            *(uint4*)(vl)     = *(const uint4*)(vb0);
            *(uint4*)(vl + 4) = *(const uint4*)(vb0 + 4);
            *(uint4*)(vh)     = *(const uint4*)(vb1);
            *(uint4*)(vh + 4) = *(const uint4*)(vb1 + 4);
            #pragma unroll
            for (int dt = 0; dt < 8; dt++)
                mma8(o[dt], pl0[kk], pl1[kk], ph0[kk], ph1[kk], vl[dt], vh[dt]);
        }
        __syncthreads();   // V buffer free for next iteration's stream
    }

    // ---- partial epilogue: unnormalized O + (m, l)  (VALIDATED R7) ----
    size_t base = (size_t)split*MTOT + (size_t)b*SL + blockIdx.x*64 + wid*16;
    float* O0 = g_part + (base + g) * DKH;
    float* O1 = g_part + (base + g + 8) * DKH;
    #pragma unroll
    for (int dt = 0; dt < 8; dt++) {
        int c = dt*8 + 2*tg;
        *(float2*)(O0 + c) = make_float2(o[dt][0], o[dt][1]);
        *(float2*)(O1 + c) = make_float2(o[dt][2], o[dt][3]);
    }
    if (tg == 0) {
        g_ml[(base + g)*2]         = m0;
        g_ml[(base + g)*2 + 1]     = l0;
        g_ml[(base + g + 8)*2]     = m1;
        g_ml[(base + g + 8)*2 + 1] = l1;
    }
}

// ============================================================================
// Kernel 3: split merge (VALIDATED R7).  One thread per float2 of output.
// ============================================================================
__global__ __launch_bounds__(256) void merge_kernel(float* __restrict__ out)
{
    int t = blockIdx.x * 256 + threadIdx.x;      // MTOT*32 threads
    int row = t >> 5;
    int cp  = (t & 31) * 2;

    float m[NSPLIT], l[NSPLIT];
    #pragma unroll
    for (int s = 0; s < NSPLIT; s++) {
        m[s] = g_ml[((size_t)s*MTOT + row)*2];
        l[s] = g_ml[((size_t)s*MTOT + row)*2 + 1];
    }
    float M = m[0];
    #pragma unroll
    for (int s = 1; s < NSPLIT; s++) M = fmaxf(M, m[s]);
    float w[NSPLIT], L = 0.f;
    #pragma unroll
    for (int s = 0; s < NSPLIT; s++) { w[s] = ex2(m[s] - M); L += w[s]*l[s]; }

    float ax = 0.f, ay = 0.f;
    #pragma unroll
    for (int s = 0; s < NSPLIT; s++) {
        float2 v = *(const float2*)(g_part + ((size_t)s*MTOT + row)*DKH + cp);
        ax += w[s]*v.x; ay += w[s]*v.y;
    }
    float invL = 1.f / L;
    *(float2*)(out + (size_t)row*DKH + cp) = make_float2(ax*invL, ay*invL);
}

// ============================================================================
extern "C" void kernel_launch(void* const* d_in, const int* in_sizes, int n_in,
                              void* d_out, int out_size)
{
    const float* in1 = (const float*)d_in[0];
    const float* in2 = (const float*)d_in[1];
    const float* Wq  = (const float*)d_in[2];
    const float* bq  = (const float*)d_in[3];
    const float* Wk  = (const float*)d_in[4];
    const float* bk  = (const float*)d_in[5];
    const float* Wv  = (const float*)d_in[6];
    const float* bv  = (const float*)d_in[7];
    float* out = (float*)d_out;

    cudaFuncSetAttribute(attn_kernel,
                         cudaFuncAttributeMaxDynamicSharedMemorySize, SMEM_ATTN);

    proj_kernel<<<dim3(MTOT/128, 3), 256>>>(in1, in2, Wq, bq, Wk, bk, Wv, bv);
    attn_kernel<<<dim3(SL/64, NB, NSPLIT), 128, SMEM_ATTN>>>();
    merge_kernel<<<(MTOT*32)/256, 256>>>(out);
}